// round 3
// baseline (speedup 1.0000x reference)
#include <cuda_runtime.h>
#include <cstdint>

#define KIDS 64
#define NCANDS 16
#define NTHR 512
#define MAXBLK 4096   // supports HW up to 4096*NTHR*4 = 8M pixels

// Per-block partials: every block writes all KIDS slots each launch before any
// read (ordered by the completion counter + fences), so no init pass is needed.
__device__ unsigned long long g_bpair[MAXBLK * KIDS];  // (first<<32)|second
__device__ int                g_bcnt [MAXBLK * KIDS];
__device__ unsigned int       g_done = 0;              // reset by last block

__device__ __forceinline__ uint32_t rotl32(uint32_t v, int d) {
    return __funnelshift_l(v, v, d);
}

// JAX threefry2x32 (20 rounds), bit-exact.
__device__ __forceinline__ void tf2x32(uint32_t k0, uint32_t k1,
                                       uint32_t x0, uint32_t x1,
                                       uint32_t& o0, uint32_t& o1) {
    uint32_t k2 = k0 ^ k1 ^ 0x1BD11BDAu;
    x0 += k0; x1 += k1;
#define R_(r) { x0 += x1; x1 = rotl32(x1, (r)); x1 ^= x0; }
    R_(13) R_(15) R_(26) R_(6)   x0 += k1; x1 += k2 + 1u;
    R_(17) R_(29) R_(16) R_(24)  x0 += k2; x1 += k0 + 2u;
    R_(13) R_(15) R_(26) R_(6)   x0 += k0; x1 += k1 + 3u;
    R_(17) R_(29) R_(16) R_(24)  x0 += k1; x1 += k2 + 4u;
    R_(13) R_(15) R_(26) R_(6)   x0 += k2; x1 += k0 + 5u;
#undef R_
    o0 = x0; o1 = x1;
}

// Two-smallest merge: (f1,s1) + (f2,s2) -> (min-two of the union)
__device__ __forceinline__ void merge2(unsigned& f1, unsigned& s1,
                                       unsigned f2, unsigned s2) {
    unsigned nf = min(f1, f2);
    unsigned ns = min(max(f1, f2), min(s1, s2));
    f1 = nf; s1 = ns;
}

__global__ void __launch_bounds__(NTHR)
fused_kernel(const float* __restrict__ sem, const int* __restrict__ mask,
             float* __restrict__ out, int HW, int BC) {
    __shared__ int sF[KIDS], sS[KIDS], sC[KIDS];
    __shared__ float sPer[KIDS];
    __shared__ int   sVal[KIDS];
    __shared__ int sLast;

    int t = threadIdx.x, warp = t >> 5, lane = t & 31;
    int bid = blockIdx.x;

    if (t < KIDS) { sF[t] = 0x7FFFFFFF; sS[t] = 0x7FFFFFFF; sC[t] = 0; }
    __syncthreads();

    // ---- phase 1: per-block first/count over one int4 per thread ----
    int base = (bid * NTHR + t) * 4;
    int id0 = -1, id1 = -1, id2 = -1, id3 = -1;
    bool full = (base + 3 < HW);
    if (full) {
        int4 m = *reinterpret_cast<const int4*>(mask + base);
        id0 = m.x & (KIDS - 1); id1 = m.y & (KIDS - 1);
        id2 = m.z & (KIDS - 1); id3 = m.w & (KIDS - 1);
        atomicMin(&sF[id0], base);
        atomicMin(&sF[id1], base + 1);
        atomicMin(&sF[id2], base + 2);
        atomicMin(&sF[id3], base + 3);
        atomicAdd(&sC[id0], 1); atomicAdd(&sC[id1], 1);
        atomicAdd(&sC[id2], 1); atomicAdd(&sC[id3], 1);
    } else {
        for (int j = 0; j < 4; j++) {
            int idx = base + j;
            if (idx < HW) {
                int id = mask[idx] & (KIDS - 1);
                atomicMin(&sF[id], idx);
                atomicAdd(&sC[id], 1);
            }
        }
    }
    __syncthreads();
    // ---- phase 2: per-block second ----
    if (full) {
        if (base     != sF[id0]) atomicMin(&sS[id0], base);
        if (base + 1 != sF[id1]) atomicMin(&sS[id1], base + 1);
        if (base + 2 != sF[id2]) atomicMin(&sS[id2], base + 2);
        if (base + 3 != sF[id3]) atomicMin(&sS[id3], base + 3);
    } else {
        for (int j = 0; j < 4; j++) {
            int idx = base + j;
            if (idx < HW) {
                int id = mask[idx] & (KIDS - 1);
                if (idx != sF[id]) atomicMin(&sS[id], idx);
            }
        }
    }
    __syncthreads();

    // ---- write partials (every slot, every launch) ----
    if (t < KIDS) {
        g_bpair[bid * KIDS + t] =
            ((unsigned long long)(unsigned)sF[t] << 32) | (unsigned)sS[t];
        g_bcnt[bid * KIDS + t] = sC[t];
    }
    __threadfence();
    if (t == 0) {
        unsigned prev = atomicAdd(&g_done, 1u);
        sLast = (prev == gridDim.x - 1) ? 1 : 0;
    }
    __syncthreads();
    if (!sLast) return;

    // =========== last block: reduce partials + finalize ===========
    __threadfence();
    int nblk = gridDim.x;

    // child key k2 of split(key(1)) — partitionable threefry path
    uint32_t kk0, kk1;
    tf2x32(0u, 1u, 0u, 1u, kk0, kk1);

    // warp w handles ids w, w+16, w+32, w+48 (NTHR=512 -> 16 warps)
    for (int k = warp; k < KIDS; k += (NTHR >> 5)) {
        unsigned f = 0x7FFFFFFFu, s = 0x7FFFFFFFu;
        int cnt = 0;
        for (int b = lane; b < nblk; b += 32) {
            unsigned long long p = g_bpair[b * KIDS + k];
            merge2(f, s, (unsigned)(p >> 32), (unsigned)p);
            cnt += g_bcnt[b * KIDS + k];
        }
        #pragma unroll
        for (int o = 16; o; o >>= 1) {
            unsigned f2 = __shfl_down_sync(0xffffffffu, f, o);
            unsigned s2 = __shfl_down_sync(0xffffffffu, s, o);
            cnt += __shfl_down_sync(0xffffffffu, cnt, o);
            merge2(f, s, f2, s2);
        }
        f = __shfl_sync(0xffffffffu, f, 0);
        s = __shfl_sync(0xffffffffu, s, 0);
        cnt = __shfl_sync(0xffffffffu, cnt, 0);
        int fi = (int)min(f, (unsigned)(HW - 1));
        int si = (int)min(s, (unsigned)(HW - 1));

        // random negative: first of 16 candidates whose mask id differs
        int cand = 0; bool ok = false;
        if (lane < NCANDS) {
            uint32_t o0, o1;
            tf2x32(kk0, kk1, 0u, (uint32_t)(k * NCANDS + lane), o0, o1);
            cand = (int)((o0 ^ o1) % (uint32_t)HW);
            ok = (mask[cand] != k);
        }
        unsigned bal = __ballot_sync(0xffffffffu, ok);
        int pick = bal ? (__ffs(bal) - 1) : 0;
        int neg = __shfl_sync(0xffffffffu, cand, pick);

        // pairwise distances over BC channels, lanes parallel over channels
        float dap = 0.f, dan = 0.f;
        for (int c = lane; c < BC; c += 32) {
            const float* bp = sem + (size_t)c * (size_t)HW;
            float av  = __ldg(bp + fi);
            float pv  = __ldg(bp + si);
            float nv2 = __ldg(bp + neg);
            float d1 = av - pv  + 1e-6f;
            float d2 = av - nv2 + 1e-6f;
            dap = fmaf(d1, d1, dap);
            dan = fmaf(d2, d2, dan);
        }
        #pragma unroll
        for (int o = 16; o; o >>= 1) {
            dap += __shfl_down_sync(0xffffffffu, dap, o);
            dan += __shfl_down_sync(0xffffffffu, dan, o);
        }
        if (lane == 0) {
            bool valid = (cnt >= 2) && (k != 0);
            float per = fmaxf(sqrtf(dap) - sqrtf(dan) + 1.0f, 0.0f);
            sPer[k] = valid ? per : 0.0f;
            sVal[k] = valid ? 1 : 0;
        }
    }
    __syncthreads();
    if (t == 0) {  // deterministic serial reduction over 64 ids
        float tot = 0.f; int c = 0;
        for (int k = 0; k < KIDS; k++) { tot += sPer[k]; c += sVal[k]; }
        out[0] = (c > 0) ? tot / (float)c : 0.0f;
        g_done = 0;  // make the launch graph-replayable
    }
}

extern "C" void kernel_launch(void* const* d_in, const int* in_sizes, int n_in,
                              void* d_out, int out_size) {
    const float* sem  = (const float*)d_in[0];
    const int*   mask = (const int*)d_in[1];
    float*       out  = (float*)d_out;
    int HW = in_sizes[1];
    int BC = in_sizes[0] / HW;

    int per_block = NTHR * 4;
    int blocks = (HW + per_block - 1) / per_block;
    if (blocks > MAXBLK) blocks = MAXBLK;  // (HW=1M -> 512 blocks; guard only)
    fused_kernel<<<blocks, NTHR>>>(sem, mask, out, HW, BC);
}

// round 4
// speedup vs baseline: 2.2462x; 2.2462x over previous
#include <cuda_runtime.h>
#include <cstdint>

#define KIDS 64
#define NCANDS 16
#define NTHR 512
#define SENT 0x7FFFFFFFu

// Statically initialized sentinels; the last block of every launch resets them,
// so every launch (and every graph replay) starts from this exact state.
#define R8 SENT, SENT, SENT, SENT, SENT, SENT, SENT, SENT
__device__ unsigned g_f[KIDS] = { R8, R8, R8, R8, R8, R8, R8, R8 };
__device__ unsigned g_s[KIDS] = { R8, R8, R8, R8, R8, R8, R8, R8 };
#undef R8
__device__ unsigned g_done = 0;

__device__ __forceinline__ uint32_t rotl32(uint32_t v, int d) {
    return __funnelshift_l(v, v, d);
}

// JAX threefry2x32 (20 rounds), bit-exact.
__device__ __forceinline__ void tf2x32(uint32_t k0, uint32_t k1,
                                       uint32_t x0, uint32_t x1,
                                       uint32_t& o0, uint32_t& o1) {
    uint32_t k2 = k0 ^ k1 ^ 0x1BD11BDAu;
    x0 += k0; x1 += k1;
#define R_(r) { x0 += x1; x1 = rotl32(x1, (r)); x1 ^= x0; }
    R_(13) R_(15) R_(26) R_(6)   x0 += k1; x1 += k2 + 1u;
    R_(17) R_(29) R_(16) R_(24)  x0 += k2; x1 += k0 + 2u;
    R_(13) R_(15) R_(26) R_(6)   x0 += k0; x1 += k1 + 3u;
    R_(17) R_(29) R_(16) R_(24)  x0 += k1; x1 += k2 + 4u;
    R_(13) R_(15) R_(26) R_(6)   x0 += k2; x1 += k0 + 5u;
#undef R_
    o0 = x0; o1 = x1;
}

__global__ void __launch_bounds__(NTHR)
fused_kernel(const float* __restrict__ sem, const int* __restrict__ mask,
             float* __restrict__ out, int HW, int BC) {
    __shared__ int sF[KIDS], sS[KIDS];
    __shared__ float sPer[KIDS];
    __shared__ int   sVal[KIDS];
    __shared__ int sLast;

    int t = threadIdx.x, warp = t >> 5, lane = t & 31;
    int bid = blockIdx.x;

    if (t < KIDS) { sF[t] = (int)SENT; sS[t] = (int)SENT; }
    __syncthreads();

    // ---- phase 1: block-local FIRST per id (read-filtered smem atomics) ----
    int base = (bid * NTHR + t) * 4;
    int id0 = -1, id1 = -1, id2 = -1, id3 = -1;
    bool full = (base + 3 < HW);
    if (full) {
        int4 m = *reinterpret_cast<const int4*>(mask + base);
        id0 = m.x & (KIDS - 1); id1 = m.y & (KIDS - 1);
        id2 = m.z & (KIDS - 1); id3 = m.w & (KIDS - 1);
        if (base     < sF[id0]) atomicMin(&sF[id0], base);
        if (base + 1 < sF[id1]) atomicMin(&sF[id1], base + 1);
        if (base + 2 < sF[id2]) atomicMin(&sF[id2], base + 2);
        if (base + 3 < sF[id3]) atomicMin(&sF[id3], base + 3);
    } else {
        for (int j = 0; j < 4; j++) {
            int idx = base + j;
            if (idx < HW) {
                int id = mask[idx] & (KIDS - 1);
                if (idx < sF[id]) atomicMin(&sF[id], idx);
            }
        }
    }
    __syncthreads();
    // ---- phase 2: block-local SECOND per id ----
    if (full) {
        if (base     != sF[id0] && base     < sS[id0]) atomicMin(&sS[id0], base);
        if (base + 1 != sF[id1] && base + 1 < sS[id1]) atomicMin(&sS[id1], base + 1);
        if (base + 2 != sF[id2] && base + 2 < sS[id2]) atomicMin(&sS[id2], base + 2);
        if (base + 3 != sF[id3] && base + 3 < sS[id3]) atomicMin(&sS[id3], base + 3);
    } else {
        for (int j = 0; j < 4; j++) {
            int idx = base + j;
            if (idx < HW) {
                int id = mask[idx] & (KIDS - 1);
                if (idx != sF[id] && idx < sS[id]) atomicMin(&sS[id], idx);
            }
        }
    }
    __syncthreads();

    // ---- lock-free two-min merge into globals (no CAS loops) ----
    // prev = atomicMin(g_f, f); displaced max(f,prev) and the local second are
    // second-candidates via filtered atomicMin(g_s, .). Linearizable.
    if (t < KIDS) {
        unsigned f = (unsigned)sF[t];
        if (f != SENT) {
            unsigned s = (unsigned)sS[t];
            unsigned cand = SENT;
            if (f < __ldcg(&g_f[t])) {
                unsigned prev = atomicMin(&g_f[t], f);
                if (prev != SENT) cand = max(f, prev);  // displaced value
            } else {
                cand = f;   // f can't be global first; it's a second-candidate
            }
            if (cand < __ldcg(&g_s[t])) atomicMin(&g_s[t], cand);
            if (s != SENT && s < __ldcg(&g_s[t])) atomicMin(&g_s[t], s);
        }
    }
    __threadfence();
    if (t == 0) {
        unsigned prev = atomicAdd(&g_done, 1u);
        sLast = (prev == gridDim.x - 1) ? 1 : 0;
    }
    __syncthreads();
    if (!sLast) return;

    // =========== last block: finalize (reads just 64 global pairs) ===========
    __threadfence();

    // child key k2 of split(key(1)) — partitionable threefry path
    uint32_t kk0, kk1;
    tf2x32(0u, 1u, 0u, 1u, kk0, kk1);

    for (int k = warp; k < KIDS; k += (NTHR >> 5)) {
        unsigned f = __ldcg(&g_f[k]);
        unsigned s = __ldcg(&g_s[k]);
        bool valid = (s != SENT) && (k != 0);   // second exists <=> count >= 2
        int fi = (int)min(f, (unsigned)(HW - 1));
        int si = (int)min(s, (unsigned)(HW - 1));

        // random negative: first of 16 candidates whose mask id differs
        int cand = 0; bool ok = false;
        if (lane < NCANDS) {
            uint32_t o0, o1;
            tf2x32(kk0, kk1, 0u, (uint32_t)(k * NCANDS + lane), o0, o1);
            cand = (int)((o0 ^ o1) % (uint32_t)HW);
            ok = (mask[cand] != k);
        }
        unsigned bal = __ballot_sync(0xffffffffu, ok);
        int pick = bal ? (__ffs(bal) - 1) : 0;
        int neg = __shfl_sync(0xffffffffu, cand, pick);

        // pairwise distances over BC channels, lanes parallel over channels
        float dap = 0.f, dan = 0.f;
        for (int c = lane; c < BC; c += 32) {
            const float* bp = sem + (size_t)c * (size_t)HW;
            float av  = __ldg(bp + fi);
            float pv  = __ldg(bp + si);
            float nv2 = __ldg(bp + neg);
            float d1 = av - pv  + 1e-6f;
            float d2 = av - nv2 + 1e-6f;
            dap = fmaf(d1, d1, dap);
            dan = fmaf(d2, d2, dan);
        }
        #pragma unroll
        for (int o = 16; o; o >>= 1) {
            dap += __shfl_down_sync(0xffffffffu, dap, o);
            dan += __shfl_down_sync(0xffffffffu, dan, o);
        }
        if (lane == 0) {
            float per = fmaxf(sqrtf(dap) - sqrtf(dan) + 1.0f, 0.0f);
            sPer[k] = valid ? per : 0.0f;
            sVal[k] = valid ? 1 : 0;
        }
    }
    __syncthreads();
    if (t == 0) {  // deterministic serial reduction over 64 ids
        float tot = 0.f; int c = 0;
        for (int k = 0; k < KIDS; k++) { tot += sPer[k]; c += sVal[k]; }
        out[0] = (c > 0) ? tot / (float)c : 0.0f;
        g_done = 0;                      // reset for next graph replay
    }
    if (t < KIDS) { g_f[t] = SENT; g_s[t] = SENT; }   // reset sentinels
}

extern "C" void kernel_launch(void* const* d_in, const int* in_sizes, int n_in,
                              void* d_out, int out_size) {
    const float* sem  = (const float*)d_in[0];
    const int*   mask = (const int*)d_in[1];
    float*       out  = (float*)d_out;
    int HW = in_sizes[1];
    int BC = in_sizes[0] / HW;

    int per_block = NTHR * 4;
    int blocks = (HW + per_block - 1) / per_block;
    fused_kernel<<<blocks, NTHR>>>(sem, mask, out, HW, BC);
}

// round 6
// speedup vs baseline: 2.5117x; 1.1182x over previous
#include <cuda_runtime.h>
#include <cstdint>

#define KIDS 64
#define NCANDS 16
#define NTHR 1024
#define PFX_I4 8                 // int4 loads per thread in the prefix scan
#define SENTI 0x7FFFFFFF

__device__ __forceinline__ uint32_t rotl32(uint32_t v, int d) {
    return __funnelshift_l(v, v, d);
}

// JAX threefry2x32 (20 rounds), bit-exact.
__device__ __forceinline__ void tf2x32(uint32_t k0, uint32_t k1,
                                       uint32_t x0, uint32_t x1,
                                       uint32_t& o0, uint32_t& o1) {
    uint32_t k2 = k0 ^ k1 ^ 0x1BD11BDAu;
    x0 += k0; x1 += k1;
#define R_(r) { x0 += x1; x1 = rotl32(x1, (r)); x1 ^= x0; }
    R_(13) R_(15) R_(26) R_(6)   x0 += k1; x1 += k2 + 1u;
    R_(17) R_(29) R_(16) R_(24)  x0 += k2; x1 += k0 + 2u;
    R_(13) R_(15) R_(26) R_(6)   x0 += k0; x1 += k1 + 3u;
    R_(17) R_(29) R_(16) R_(24)  x0 += k1; x1 += k2 + 4u;
    R_(13) R_(15) R_(26) R_(6)   x0 += k2; x1 += k0 + 5u;
#undef R_
    o0 = x0; o1 = x1;
}

__global__ void __launch_bounds__(NTHR)
single_kernel(const float* __restrict__ sem, const int* __restrict__ mask,
              float* __restrict__ out, int HW, int BC) {
    __shared__ int sF[KIDS], sS[KIDS], sNeg[KIDS];
    __shared__ float sPer[KIDS];
    __shared__ int   sVal[KIDS];

    int t = threadIdx.x, warp = t >> 5, lane = t & 31;

    if (t < KIDS) { sF[t] = SENTI; sS[t] = SENTI; }
    __syncthreads();

    // ---- negatives first (independent of the scan; overlaps its latency) ----
    uint32_t kk0, kk1;
    tf2x32(0u, 1u, 0u, 1u, kk0, kk1);     // child key of split(key(1))
    for (int k = warp; k < KIDS; k += (NTHR >> 5)) {
        int cand = 0; bool ok = false;
        if (lane < NCANDS) {
            uint32_t o0, o1;
            tf2x32(kk0, kk1, 0u, (uint32_t)(k * NCANDS + lane), o0, o1);
            cand = (int)((o0 ^ o1) % (uint32_t)HW);
            ok = (__ldg(mask + cand) != k);
        }
        unsigned bal = __ballot_sync(0xffffffffu, ok);
        int pick = bal ? (__ffs(bal) - 1) : 0;
        int neg = __shfl_sync(0xffffffffu, cand, pick);
        if (lane == 0) sNeg[k] = neg;
    }

    // ---- single-phase two-min update (displaced-value atomicMin trick) ----
    auto upd = [&](int idx, int id) {
        int cand;
        if (idx < sF[id]) {
            int prev = atomicMin(&sF[id], idx);
            cand = (prev == SENTI) ? SENTI : max(idx, prev);  // displaced value
        } else {
            cand = idx;            // not a first; candidate for second
        }
        if (cand < sS[id]) atomicMin(&sS[id], cand);
    };

    // ---- prefix scan: first PFX pixels decide first/second if complete ----
    int PFX = min(HW & ~3, NTHR * 4 * PFX_I4);   // 32768 for HW=1M
    {
        int4 v[PFX_I4];
        bool hv[PFX_I4];
        #pragma unroll
        for (int i = 0; i < PFX_I4; i++) {        // batched loads, MLP=8
            int p = (i * NTHR + t) * 4;
            hv[i] = (p < PFX);
            if (hv[i]) v[i] = *reinterpret_cast<const int4*>(mask + p);
        }
        #pragma unroll
        for (int i = 0; i < PFX_I4; i++) if (hv[i]) {
            int p = (i * NTHR + t) * 4;
            upd(p,     v[i].x & (KIDS - 1));
            upd(p + 1, v[i].y & (KIDS - 1));
            upd(p + 2, v[i].z & (KIDS - 1));
            upd(p + 3, v[i].w & (KIDS - 1));
        }
    }

    // ---- completeness check: every id 1..63 has a second in the prefix ----
    int mydone = (t < KIDS) ? ((t == 0 || sS[t] != SENTI) ? 1 : 0) : 1;
    int cnt = __syncthreads_count(mydone);
    if (cnt != NTHR) {
        // exact fallback: scan the remaining pixels (correct for any input)
        for (int p = PFX + t * 4; p + 3 < HW; p += NTHR * 4) {
            int4 m = *reinterpret_cast<const int4*>(mask + p);
            upd(p,     m.x & (KIDS - 1));
            upd(p + 1, m.y & (KIDS - 1));
            upd(p + 2, m.z & (KIDS - 1));
            upd(p + 3, m.w & (KIDS - 1));
        }
        for (int p = (HW & ~3) + t; p < HW; p += NTHR)  // scalar tail
            upd(p, mask[p] & (KIDS - 1));
        __syncthreads();
    }

    // ---- finalize: gathers + triplet loss (all smem-resident state) ----
    for (int k = warp; k < KIDS; k += (NTHR >> 5)) {
        int f = sF[k], s = sS[k];
        bool valid = (s != SENTI) && (k != 0);   // second exists <=> count >= 2
        int fi = min(f, HW - 1);
        int si = min(s, HW - 1);
        int neg = sNeg[k];

        float dap = 0.f, dan = 0.f;
        for (int c = lane; c < BC; c += 32) {
            const float* bp = sem + (size_t)c * (size_t)HW;
            float av  = __ldg(bp + fi);
            float pv  = __ldg(bp + si);
            float nv2 = __ldg(bp + neg);
            float d1 = av - pv  + 1e-6f;
            float d2 = av - nv2 + 1e-6f;
            dap = fmaf(d1, d1, dap);
            dan = fmaf(d2, d2, dan);
        }
        #pragma unroll
        for (int o = 16; o; o >>= 1) {
            dap += __shfl_down_sync(0xffffffffu, dap, o);
            dan += __shfl_down_sync(0xffffffffu, dan, o);
        }
        if (lane == 0) {
            float per = fmaxf(sqrtf(dap) - sqrtf(dan) + 1.0f, 0.0f);
            sPer[k] = valid ? per : 0.0f;
            sVal[k] = valid ? 1 : 0;
        }
    }
    __syncthreads();
    if (t == 0) {   // deterministic serial reduction over 64 ids
        float tot = 0.f; int c = 0;
        for (int k = 0; k < KIDS; k++) { tot += sPer[k]; c += sVal[k]; }
        out[0] = (c > 0) ? tot / (float)c : 0.0f;
    }
}

extern "C" void kernel_launch(void* const* d_in, const int* in_sizes, int n_in,
                              void* d_out, int out_size) {
    const float* sem  = (const float*)d_in[0];
    const int*   mask = (const int*)d_in[1];
    float*       out  = (float*)d_out;
    int HW = in_sizes[1];
    int BC = in_sizes[0] / HW;

    single_kernel<<<1, NTHR>>>(sem, mask, out, HW, BC);
}

// round 7
// speedup vs baseline: 2.8234x; 1.1241x over previous
#include <cuda_runtime.h>
#include <cstdint>

#define KIDS 64
#define NCANDS 16
#define NTHR 1024
#define WIN  (NTHR * 4)          // 4096-pixel staging window (16 KB)
#define SENTI 0x7FFFFFFF

__device__ __forceinline__ uint32_t rotl32(uint32_t v, int d) {
    return __funnelshift_l(v, v, d);
}

// JAX threefry2x32 (20 rounds), bit-exact.
__device__ __forceinline__ void tf2x32(uint32_t k0, uint32_t k1,
                                       uint32_t x0, uint32_t x1,
                                       uint32_t& o0, uint32_t& o1) {
    uint32_t k2 = k0 ^ k1 ^ 0x1BD11BDAu;
    x0 += k0; x1 += k1;
#define R_(r) { x0 += x1; x1 = rotl32(x1, (r)); x1 ^= x0; }
    R_(13) R_(15) R_(26) R_(6)   x0 += k1; x1 += k2 + 1u;
    R_(17) R_(29) R_(16) R_(24)  x0 += k2; x1 += k0 + 2u;
    R_(13) R_(15) R_(26) R_(6)   x0 += k0; x1 += k1 + 3u;
    R_(17) R_(29) R_(16) R_(24)  x0 += k1; x1 += k2 + 4u;
    R_(13) R_(15) R_(26) R_(6)   x0 += k2; x1 += k0 + 5u;
#undef R_
    o0 = x0; o1 = x1;
}

// Warp-uniform: find the two smallest matching pixel positions of id k in the
// chunk (x = this lane's 4 consecutive ids, base = global pixel of chunk start).
// Updates (f, s, done) registers, replicated across the warp. No atomics.
__device__ __forceinline__ void scan_chunk(int4 x, int k, int base,
                                           int& f, int& s, bool& done) {
    unsigned m = (x.x == k ? 1u : 0u) | (x.y == k ? 2u : 0u) |
                 (x.z == k ? 4u : 0u) | (x.w == k ? 8u : 0u);
    unsigned b = __ballot_sync(0xffffffffu, m != 0u);
    if (!b) return;
    int l1 = __ffs(b) - 1;
    unsigned m1 = __shfl_sync(0xffffffffu, m, l1);
    int pos1 = base + l1 * 4 + (__ffs(m1) - 1);
    int pos2 = -1;
    unsigned m1r = m1 & (m1 - 1);
    if (m1r) {
        pos2 = base + l1 * 4 + (__ffs(m1r) - 1);
    } else {
        unsigned b2 = b & (b - 1);
        if (b2) {
            int l2 = __ffs(b2) - 1;
            unsigned m2 = __shfl_sync(0xffffffffu, m, l2);
            pos2 = base + l2 * 4 + (__ffs(m2) - 1);
        }
    }
    if (f == SENTI) {
        f = pos1;
        if (pos2 >= 0) { s = pos2; done = true; }
    } else {
        s = pos1; done = true;
    }
}

__global__ void __launch_bounds__(NTHR)
single_kernel(const float* __restrict__ sem, const int* __restrict__ mask,
              float* __restrict__ out, int HW, int BC) {
    __shared__ int sIds[WIN];
    __shared__ int sF[KIDS], sS[KIDS], sNeg[KIDS];
    __shared__ float sPer[KIDS];
    __shared__ int   sVal[KIDS];

    int t = threadIdx.x, warp = t >> 5, lane = t & 31;

    // ---- negatives (memory latency overlaps the window-0 staging load) ----
    uint32_t kk0, kk1;
    tf2x32(0u, 1u, 0u, 1u, kk0, kk1);     // child key of split(key(1))
    for (int k = warp; k < KIDS; k += (NTHR >> 5)) {
        int cand = 0; bool ok = false;
        if (lane < NCANDS) {
            uint32_t o0, o1;
            tf2x32(kk0, kk1, 0u, (uint32_t)(k * NCANDS + lane), o0, o1);
            cand = (int)((o0 ^ o1) % (uint32_t)HW);
            ok = (__ldg(mask + cand) != k);
        }
        unsigned bal = __ballot_sync(0xffffffffu, ok);
        int pick = bal ? (__ffs(bal) - 1) : 0;
        int neg = __shfl_sync(0xffffffffu, cand, pick);
        if (lane == 0) sNeg[k] = neg;
    }

    // ---- windowed ballot scan: warp w owns ids 2w and 2w+1 ----
    int k0 = warp * 2, k1 = warp * 2 + 1;
    int f0 = SENTI, s0 = SENTI, f1 = SENTI, s1 = SENTI;
    bool d0 = (k0 == 0);     // background id skipped (always invalid)
    bool d1 = false;

    for (int w0 = 0; w0 < HW; w0 += WIN) {
        // stage window into smem (coalesced; OOB filled with -1 = no match)
        int p = w0 + t * 4;
        int4 v = make_int4(-1, -1, -1, -1);
        if (p + 3 < HW) {
            v = *reinterpret_cast<const int4*>(mask + p);
        } else {
            if (p     < HW) v.x = mask[p];
            if (p + 1 < HW) v.y = mask[p + 1];
            if (p + 2 < HW) v.z = mask[p + 2];
        }
        *reinterpret_cast<int4*>(sIds + t * 4) = v;
        __syncthreads();

        if (!(d0 && d1)) {
            #pragma unroll 1
            for (int ch = 0; ch < WIN / 128; ch++) {
                int4 x = *reinterpret_cast<const int4*>(sIds + ch * 128 + lane * 4);
                int base = w0 + ch * 128;
                if (!d0) scan_chunk(x, k0, base, f0, s0, d0);
                if (!d1) scan_chunk(x, k1, base, f1, s1, d1);
                if (d0 && d1) break;
            }
        }
        // barrier doubles as WAR guard for next window's staging
        bool alldone = d0 && d1;
        if (__syncthreads_count(alldone ? 1 : 0) == NTHR) break;
    }
    if (lane == 0) { sF[k0] = f0; sS[k0] = s0; sF[k1] = f1; sS[k1] = s1; }
    __syncthreads();

    // ---- finalize: batched gathers + triplet loss ----
    for (int k = warp; k < KIDS; k += (NTHR >> 5)) {
        int f = sF[k], s = sS[k];
        bool valid = (s != SENTI) && (k != 0);   // second exists <=> count >= 2
        int fi = min(f, HW - 1);
        int si = min(s, HW - 1);
        int neg = sNeg[k];

        float dap = 0.f, dan = 0.f;
        #pragma unroll
        for (int i = 0; i < 4; i++) {            // covers BC <= 128 (BC = 76)
            int c = lane + i * 32;
            if (c < BC) {
                size_t off = (size_t)c * (size_t)HW;
                float av  = __ldg(sem + off + fi);
                float pv  = __ldg(sem + off + si);
                float nv2 = __ldg(sem + off + neg);
                float e1 = av - pv  + 1e-6f;
                float e2 = av - nv2 + 1e-6f;
                dap = fmaf(e1, e1, dap);
                dan = fmaf(e2, e2, dan);
            }
        }
        for (int c = lane + 128; c < BC; c += 32) {   // generic tail (unused here)
            size_t off = (size_t)c * (size_t)HW;
            float av  = __ldg(sem + off + fi);
            float pv  = __ldg(sem + off + si);
            float nv2 = __ldg(sem + off + neg);
            float e1 = av - pv  + 1e-6f;
            float e2 = av - nv2 + 1e-6f;
            dap = fmaf(e1, e1, dap);
            dan = fmaf(e2, e2, dan);
        }
        #pragma unroll
        for (int o = 16; o; o >>= 1) {
            dap += __shfl_down_sync(0xffffffffu, dap, o);
            dan += __shfl_down_sync(0xffffffffu, dan, o);
        }
        if (lane == 0) {
            float per = fmaxf(sqrtf(dap) - sqrtf(dan) + 1.0f, 0.0f);
            sPer[k] = valid ? per : 0.0f;
            sVal[k] = valid ? 1 : 0;
        }
    }
    __syncthreads();
    if (t == 0) {   // deterministic serial reduction over 64 ids
        float tot = 0.f; int c = 0;
        for (int k = 0; k < KIDS; k++) { tot += sPer[k]; c += sVal[k]; }
        out[0] = (c > 0) ? tot / (float)c : 0.0f;
    }
}

extern "C" void kernel_launch(void* const* d_in, const int* in_sizes, int n_in,
                              void* d_out, int out_size) {
    const float* sem  = (const float*)d_in[0];
    const int*   mask = (const int*)d_in[1];
    float*       out  = (float*)d_out;
    int HW = in_sizes[1];
    int BC = in_sizes[0] / HW;

    single_kernel<<<1, NTHR>>>(sem, mask, out, HW, BC);
}

// round 8
// speedup vs baseline: 3.4806x; 1.2328x over previous
#include <cuda_runtime.h>
#include <cstdint>

#define KIDS 64
#define NCANDS 16
#define NTHR 1024
#define BCH 8                    // chunks per batch: 8 x 128 px = 1024 px
#define SENTI 0x7FFFFFFF

__device__ __forceinline__ uint32_t rotl32(uint32_t v, int d) {
    return __funnelshift_l(v, v, d);
}

// JAX threefry2x32 (20 rounds), bit-exact.
__device__ __forceinline__ void tf2x32(uint32_t k0, uint32_t k1,
                                       uint32_t x0, uint32_t x1,
                                       uint32_t& o0, uint32_t& o1) {
    uint32_t k2 = k0 ^ k1 ^ 0x1BD11BDAu;
    x0 += k0; x1 += k1;
#define R_(r) { x0 += x1; x1 = rotl32(x1, (r)); x1 ^= x0; }
    R_(13) R_(15) R_(26) R_(6)   x0 += k1; x1 += k2 + 1u;
    R_(17) R_(29) R_(16) R_(24)  x0 += k2; x1 += k0 + 2u;
    R_(13) R_(15) R_(26) R_(6)   x0 += k0; x1 += k1 + 3u;
    R_(17) R_(29) R_(16) R_(24)  x0 += k1; x1 += k2 + 4u;
    R_(13) R_(15) R_(26) R_(6)   x0 += k2; x1 += k0 + 5u;
#undef R_
    o0 = x0; o1 = x1;
}

// Warp-uniform: fold the two smallest positions of id k in this 128-px chunk
// into (f, s, done). x = this lane's 4 consecutive ids. No atomics.
__device__ __forceinline__ void scan_chunk(int4 x, int k, int base,
                                           int& f, int& s, bool& done) {
    unsigned m = (x.x == k ? 1u : 0u) | (x.y == k ? 2u : 0u) |
                 (x.z == k ? 4u : 0u) | (x.w == k ? 8u : 0u);
    unsigned b = __ballot_sync(0xffffffffu, m != 0u);
    if (!b) return;
    int l1 = __ffs(b) - 1;
    unsigned m1 = __shfl_sync(0xffffffffu, m, l1);
    int pos1 = base + l1 * 4 + (__ffs(m1) - 1);
    int pos2 = -1;
    unsigned m1r = m1 & (m1 - 1);
    if (m1r) {
        pos2 = base + l1 * 4 + (__ffs(m1r) - 1);
    } else {
        unsigned b2 = b & (b - 1);
        if (b2) {
            int l2 = __ffs(b2) - 1;
            unsigned m2 = __shfl_sync(0xffffffffu, m, l2);
            pos2 = base + l2 * 4 + (__ffs(m2) - 1);
        }
    }
    if (f == SENTI) {
        f = pos1;
        if (pos2 >= 0) { s = pos2; done = true; }
    } else {
        s = pos1; done = true;
    }
}

__device__ __forceinline__ void load_batch(int4* v, const int* __restrict__ mask,
                                           int base, int HW, int lane) {
    #pragma unroll
    for (int c = 0; c < BCH; c++) {
        int p = base + c * 128 + lane * 4;
        if (p + 3 < HW) {
            v[c] = *reinterpret_cast<const int4*>(mask + p);
        } else {
            v[c] = make_int4(-1, -1, -1, -1);
            if (p     < HW) v[c].x = mask[p];
            if (p + 1 < HW) v[c].y = mask[p + 1];
            if (p + 2 < HW) v[c].z = mask[p + 2];
        }
    }
}

__global__ void __launch_bounds__(NTHR)
single_kernel(const float* __restrict__ sem, const int* __restrict__ mask,
              float* __restrict__ out, int HW, int BC) {
    __shared__ float sPer[KIDS];
    __shared__ int   sVal[KIDS];

    int t = threadIdx.x, warp = t >> 5, lane = t & 31;
    int k0 = warp * 2, k1 = k0 + 1;    // this warp owns ids k0, k1 end-to-end

    // ---- negatives: lanes 0-15 carry k0's candidates, 16-31 carry k1's ----
    uint32_t kk0, kk1;
    tf2x32(0u, 1u, 0u, 1u, kk0, kk1);            // child key of split(key(1))
    int kmine = (lane < 16) ? k0 : k1;
    uint32_t o0, o1;
    tf2x32(kk0, kk1, 0u, (uint32_t)(kmine * NCANDS + (lane & 15)), o0, o1);
    int cand = (int)((o0 ^ o1) % (uint32_t)HW);
    int candval = __ldg(mask + cand);            // gather issued...

    // ---- scan batch 0: loads issued before candval is consumed (same round) --
    int4 v[BCH];
    load_batch(v, mask, 0, HW, lane);

    // resolve negatives (first candidate whose id differs; else candidate 0)
    unsigned bal = __ballot_sync(0xffffffffu, candval != kmine);
    unsigned b0m = bal & 0xFFFFu, b1m = bal >> 16;
    int neg0 = __shfl_sync(0xffffffffu, cand, b0m ? (__ffs(b0m) - 1) : 0);
    int neg1 = __shfl_sync(0xffffffffu, cand, b1m ? (16 + __ffs(b1m) - 1) : 16);

    // ---- per-warp ballot scan, batches of 1024 px until both ids done ----
    int f0 = SENTI, s0 = SENTI, f1 = SENTI, s1 = SENTI;
    bool d0 = (k0 == 0);               // background id skipped (never valid)
    bool d1 = false;
    int base = 0;
    while (true) {
        #pragma unroll
        for (int ch = 0; ch < BCH; ch++) {
            if (!d0) scan_chunk(v[ch], k0, base + ch * 128, f0, s0, d0);
            if (!d1) scan_chunk(v[ch], k1, base + ch * 128, f1, s1, d1);
        }
        base += BCH * 128;
        if ((d0 && d1) || base >= HW) break;     // exact fallback: keep going
        load_batch(v, mask, base, HW, lane);
    }

    // ---- finalize both ids: one batched gather round, warp-local ----
    bool val0 = (s0 != SENTI) && (k0 != 0);
    bool val1 = (s1 != SENTI);
    int fi0 = min(f0, HW - 1), si0 = min(s0, HW - 1);
    int fi1 = min(f1, HW - 1), si1 = min(s1, HW - 1);

    float dap0 = 0.f, dan0 = 0.f, dap1 = 0.f, dan1 = 0.f;
    #pragma unroll
    for (int i = 0; i < 4; i++) {                // covers BC <= 128 (BC = 76)
        int c = lane + i * 32;
        if (c < BC) {
            size_t off = (size_t)c * (size_t)HW;
            float a0 = __ldg(sem + off + fi0);
            float p0 = __ldg(sem + off + si0);
            float n0 = __ldg(sem + off + neg0);
            float a1 = __ldg(sem + off + fi1);
            float p1 = __ldg(sem + off + si1);
            float n1 = __ldg(sem + off + neg1);
            float e;
            e = a0 - p0 + 1e-6f; dap0 = fmaf(e, e, dap0);
            e = a0 - n0 + 1e-6f; dan0 = fmaf(e, e, dan0);
            e = a1 - p1 + 1e-6f; dap1 = fmaf(e, e, dap1);
            e = a1 - n1 + 1e-6f; dan1 = fmaf(e, e, dan1);
        }
    }
    for (int c = lane + 128; c < BC; c += 32) {  // generic tail (unused here)
        size_t off = (size_t)c * (size_t)HW;
        float a0 = __ldg(sem + off + fi0), p0 = __ldg(sem + off + si0),
              n0 = __ldg(sem + off + neg0);
        float a1 = __ldg(sem + off + fi1), p1 = __ldg(sem + off + si1),
              n1 = __ldg(sem + off + neg1);
        float e;
        e = a0 - p0 + 1e-6f; dap0 = fmaf(e, e, dap0);
        e = a0 - n0 + 1e-6f; dan0 = fmaf(e, e, dan0);
        e = a1 - p1 + 1e-6f; dap1 = fmaf(e, e, dap1);
        e = a1 - n1 + 1e-6f; dan1 = fmaf(e, e, dan1);
    }
    #pragma unroll
    for (int o = 16; o; o >>= 1) {
        dap0 += __shfl_down_sync(0xffffffffu, dap0, o);
        dan0 += __shfl_down_sync(0xffffffffu, dan0, o);
        dap1 += __shfl_down_sync(0xffffffffu, dap1, o);
        dan1 += __shfl_down_sync(0xffffffffu, dan1, o);
    }
    if (lane == 0) {
        float per0 = fmaxf(sqrtf(dap0) - sqrtf(dan0) + 1.0f, 0.0f);
        float per1 = fmaxf(sqrtf(dap1) - sqrtf(dan1) + 1.0f, 0.0f);
        sPer[k0] = val0 ? per0 : 0.0f;  sVal[k0] = val0 ? 1 : 0;
        sPer[k1] = val1 ? per1 : 0.0f;  sVal[k1] = val1 ? 1 : 0;
    }
    __syncthreads();                    // the only block barrier
    if (t == 0) {                       // deterministic serial reduction
        float tot = 0.f; int c = 0;
        for (int k = 0; k < KIDS; k++) { tot += sPer[k]; c += sVal[k]; }
        out[0] = (c > 0) ? tot / (float)c : 0.0f;
    }
}

extern "C" void kernel_launch(void* const* d_in, const int* in_sizes, int n_in,
                              void* d_out, int out_size) {
    const float* sem  = (const float*)d_in[0];
    const int*   mask = (const int*)d_in[1];
    float*       out  = (float*)d_out;
    int HW = in_sizes[1];
    int BC = in_sizes[0] / HW;

    single_kernel<<<1, NTHR>>>(sem, mask, out, HW, BC);
}